// round 2
// baseline (speedup 1.0000x reference)
#include <cuda_runtime.h>
#include <math.h>

// Problem constants
#define EDIM   256
#define HEADS  8
#define HD     32
#define NL     1600   // local nodes (40x40)
#define NG     100    // global nodes (10x10)
#define HW     1600
#define ML     (NL*2) // 3200 rows (node-major, batch interleaved)
#define MG     (NG*2) // 200 rows

// ---------------- scratch (global memory via __device__ arrays) ----------------
__device__ float d_Gn  [MG * EDIM];   // pooled global nodes  [row=(n*2+b)][e]
__device__ float d_Ln  [ML * EDIM];   // local nodes
__device__ float d_qkvg[MG * 768];    // global GAT q|k|v
__device__ float d_qkvl[ML * 768];    // local  GAT q|k|v
__device__ float d_att [ML * EDIM];   // attention output (reused)
__device__ float d_proj[ML * EDIM];   // out-proj output (reused)
__device__ float d_gout[MG * EDIM];   // global branch after LN
__device__ float d_lout[ML * EDIM];   // local branch after LN
__device__ float d_qc  [ML * EDIM];   // cross Q
__device__ float d_kvc [MG * 512];    // cross K|V (from g_out, 100 distinct keys)
__device__ float d_catt[ML * EDIM];   // cross attention out
__device__ float d_cprj[ML * EDIM];   // cross out-proj

// ---------------- pool: 4x4 avg -> global nodes ----------------
__global__ void pool_kernel(const float* __restrict__ x, float* __restrict__ gn) {
    int blk = blockIdx.x;           // 0..199 = p*2+b
    int p = blk >> 1, b = blk & 1;
    int c = threadIdx.x;
    int pr = p / 10, pc = p % 10;
    const float* xb = x + ((size_t)b * EDIM + c) * HW;
    float s = 0.f;
#pragma unroll
    for (int dy = 0; dy < 4; dy++)
#pragma unroll
        for (int dx = 0; dx < 4; dx++)
            s += xb[(pr * 4 + dy) * 40 + pc * 4 + dx];
    gn[(size_t)blk * EDIM + c] = s * (1.0f / 16.0f);
}

// ---------------- x [B,C,HW] -> nodes [(n*2+b), C] ----------------
__global__ void to_nodes_kernel(const float* __restrict__ x, float* __restrict__ ln) {
    int n = blockIdx.x;             // 0..1599
    int c = threadIdx.x;            // 0..255
#pragma unroll
    for (int b = 0; b < 2; b++)
        ln[(size_t)(n * 2 + b) * EDIM + c] = x[((size_t)b * EDIM + c) * HW + n];
}

// ---------------- GEMM: C[M,N] = A[M,256] @ W[N,256]^T + bias[N] ----------------
// 64x64 tile, 256 threads, 4x4 register tile, K=256 fixed.
__global__ void gemm_bias_kernel(const float* __restrict__ A, const float* __restrict__ W,
                                 const float* __restrict__ bias, float* __restrict__ C,
                                 int M, int N) {
    __shared__ float As[16][68];
    __shared__ float Bs[16][68];
    int bm = blockIdx.y * 64, bn = blockIdx.x * 64;
    int tid = threadIdx.x;
    int lr = tid >> 2;          // 0..63
    int lc = (tid & 3) * 4;     // 0,4,8,12
    int tm = (tid & 15) * 4;
    int tn = (tid >> 4) * 4;
    float acc[4][4];
#pragma unroll
    for (int i = 0; i < 4; i++)
#pragma unroll
        for (int j = 0; j < 4; j++) acc[i][j] = 0.f;

    for (int k0 = 0; k0 < 256; k0 += 16) {
        float4 a4 = make_float4(0.f, 0.f, 0.f, 0.f);
        if (bm + lr < M) a4 = *(const float4*)(A + (size_t)(bm + lr) * 256 + k0 + lc);
        As[lc + 0][lr] = a4.x; As[lc + 1][lr] = a4.y; As[lc + 2][lr] = a4.z; As[lc + 3][lr] = a4.w;
        float4 b4 = *(const float4*)(W + (size_t)(bn + lr) * 256 + k0 + lc);
        Bs[lc + 0][lr] = b4.x; Bs[lc + 1][lr] = b4.y; Bs[lc + 2][lr] = b4.z; Bs[lc + 3][lr] = b4.w;
        __syncthreads();
#pragma unroll
        for (int k = 0; k < 16; k++) {
            float a0 = As[k][tm + 0], a1 = As[k][tm + 1], a2 = As[k][tm + 2], a3 = As[k][tm + 3];
            float b0 = Bs[k][tn + 0], b1 = Bs[k][tn + 1], b2 = Bs[k][tn + 2], b3 = Bs[k][tn + 3];
            acc[0][0] += a0 * b0; acc[0][1] += a0 * b1; acc[0][2] += a0 * b2; acc[0][3] += a0 * b3;
            acc[1][0] += a1 * b0; acc[1][1] += a1 * b1; acc[1][2] += a1 * b2; acc[1][3] += a1 * b3;
            acc[2][0] += a2 * b0; acc[2][1] += a2 * b1; acc[2][2] += a2 * b2; acc[2][3] += a2 * b3;
            acc[3][0] += a3 * b0; acc[3][1] += a3 * b1; acc[3][2] += a3 * b2; acc[3][3] += a3 * b3;
        }
        __syncthreads();
    }
#pragma unroll
    for (int i = 0; i < 4; i++) {
        int row = bm + tm + i;
        if (row < M) {
#pragma unroll
            for (int j = 0; j < 4; j++)
                C[(size_t)row * N + bn + tn + j] = acc[i][j] + bias[bn + tn + j];
        }
    }
}

// ---------------- GAT attention ----------------
// softmax over BATCH axis (2 values) per (h,i,j); edge bias cancels -> dropped.
// o[i,b,h,:] = sum_j a[h,b,i,j] * v[j,b,h,:]
// grid: (ceil(N/32), HEADS), block: 256
__global__ void gat_attn_kernel(const float* __restrict__ qkv, float* __restrict__ out, int N) {
    __shared__ float Qs[2][32][36];
    __shared__ float Ks[2][32][36];
    __shared__ float Vs[2][32][36];
    __shared__ float Am[2][32][33];

    const int i0 = blockIdx.x * 32;
    const int hc = blockIdx.y * 32;
    const int tid = threadIdx.x;

    // load Q tile (64 rows x 32 floats)
    {
        int idx = tid;
#pragma unroll
        for (int it = 0; it < 2; it++, idx += 256) {
            int row = idx >> 3;          // 0..63
            int q4  = (idx & 7) * 4;
            int ii = row >> 1, b = row & 1;
            float4 v = make_float4(0.f, 0.f, 0.f, 0.f);
            if (i0 + ii < N) v = *(const float4*)(qkv + (size_t)((i0 + ii) * 2 + b) * 768 + hc + q4);
            *(float4*)&Qs[b][ii][q4] = v;
        }
    }

    const int ia = tid >> 3;        // i (0..31) for both phases
    const int jg = tid & 7;         // j group: j = jg + 8*r
    const int dg = (tid & 7) * 4;   // phase-B d offset
    float o0[4] = {0.f, 0.f, 0.f, 0.f};
    float o1[4] = {0.f, 0.f, 0.f, 0.f};
    const float scale = 0.17677669529663687f;  // 1/sqrt(32)
    const int nj = (N + 31) / 32;

    for (int jt = 0; jt < nj; jt++) {
        int j0 = jt * 32;
        // load K,V tiles
        {
            int idx = tid;
#pragma unroll
            for (int it = 0; it < 2; it++, idx += 256) {
                int row = idx >> 3;
                int q4  = (idx & 7) * 4;
                int jj = row >> 1, b = row & 1;
                float4 kv = make_float4(0.f, 0.f, 0.f, 0.f);
                float4 vv = make_float4(0.f, 0.f, 0.f, 0.f);
                if (j0 + jj < N) {
                    const float* base = qkv + (size_t)((j0 + jj) * 2 + b) * 768 + hc;
                    kv = *(const float4*)(base + 256 + q4);
                    vv = *(const float4*)(base + 512 + q4);
                }
                *(float4*)&Ks[b][jj][q4] = kv;
                *(float4*)&Vs[b][jj][q4] = vv;
            }
        }
        __syncthreads();

        // phase A: scores + 2-way softmax over batch
        float s0[4] = {0.f, 0.f, 0.f, 0.f};
        float s1[4] = {0.f, 0.f, 0.f, 0.f};
#pragma unroll
        for (int d = 0; d < 32; d += 4) {
            float4 q0 = *(const float4*)&Qs[0][ia][d];
            float4 q1 = *(const float4*)&Qs[1][ia][d];
#pragma unroll
            for (int r = 0; r < 4; r++) {
                int j = jg + 8 * r;
                float4 k0 = *(const float4*)&Ks[0][j][d];
                float4 k1 = *(const float4*)&Ks[1][j][d];
                s0[r] += q0.x * k0.x + q0.y * k0.y + q0.z * k0.z + q0.w * k0.w;
                s1[r] += q1.x * k1.x + q1.y * k1.y + q1.z * k1.z + q1.w * k1.w;
            }
        }
#pragma unroll
        for (int r = 0; r < 4; r++) {
            int j = jg + 8 * r;
            float a0 = 0.f, a1 = 0.f;
            if (j0 + j < N) {
                float t0 = s0[r] * scale, t1 = s1[r] * scale;
                float m = fmaxf(t0, t1);
                float e0 = __expf(t0 - m), e1 = __expf(t1 - m);
                float inv = 1.0f / (e0 + e1);
                a0 = e0 * inv; a1 = e1 * inv;
            }
            Am[0][ia][j] = a0;
            Am[1][ia][j] = a1;
        }
        __syncthreads();

        // phase B: o += A @ V
#pragma unroll
        for (int j = 0; j < 32; j++) {
            float a0 = Am[0][ia][j];
            float a1 = Am[1][ia][j];
            float4 v0 = *(const float4*)&Vs[0][j][dg];
            float4 v1 = *(const float4*)&Vs[1][j][dg];
            o0[0] += a0 * v0.x; o0[1] += a0 * v0.y; o0[2] += a0 * v0.z; o0[3] += a0 * v0.w;
            o1[0] += a1 * v1.x; o1[1] += a1 * v1.y; o1[2] += a1 * v1.z; o1[3] += a1 * v1.w;
        }
        __syncthreads();
    }

    if (i0 + ia < N) {
        float4 w0 = make_float4(o0[0], o0[1], o0[2], o0[3]);
        float4 w1 = make_float4(o1[0], o1[1], o1[2], o1[3]);
        *(float4*)(out + (size_t)((i0 + ia) * 2 + 0) * 256 + hc + dg) = w0;
        *(float4*)(out + (size_t)((i0 + ia) * 2 + 1) * 256 + hc + dg) = w1;
    }
}

// ---------------- residual add + LayerNorm (optionally transposed final write) ----------------
__global__ void add_ln_kernel(const float* __restrict__ y, const float* __restrict__ res,
                              const float* __restrict__ g, const float* __restrict__ bt,
                              float* __restrict__ out, int transpose_out) {
    int row = blockIdx.x;
    int c = threadIdx.x;
    float v = y[(size_t)row * 256 + c] + res[(size_t)row * 256 + c];

    float s = v, s2 = v * v;
#pragma unroll
    for (int o = 16; o; o >>= 1) {
        s  += __shfl_xor_sync(0xffffffffu, s,  o);
        s2 += __shfl_xor_sync(0xffffffffu, s2, o);
    }
    __shared__ float ws[8], ws2[8];
    int w = c >> 5, l = c & 31;
    if (l == 0) { ws[w] = s; ws2[w] = s2; }
    __syncthreads();
    if (w == 0) {
        float a  = (l < 8) ? ws[l]  : 0.f;
        float a2 = (l < 8) ? ws2[l] : 0.f;
#pragma unroll
        for (int o = 4; o; o >>= 1) {
            a  += __shfl_xor_sync(0xffffffffu, a,  o);
            a2 += __shfl_xor_sync(0xffffffffu, a2, o);
        }
        if (l == 0) { ws[0] = a; ws2[0] = a2; }
    }
    __syncthreads();
    float mean = ws[0] * (1.f / 256.f);
    float var  = ws2[0] * (1.f / 256.f) - mean * mean;
    float rs = rsqrtf(var + 1e-5f);
    float o_ = (v - mean) * rs * g[c] + bt[c];
    if (transpose_out) {
        int n = row >> 1, b = row & 1;
        out[((size_t)b * 256 + c) * HW + n] = o_;
    } else {
        out[(size_t)row * 256 + c] = o_;
    }
}

// ---------------- cross attention: Q[1600 rows], K/V from the 100 distinct g_out rows ----------------
// (16x key duplication cancels exactly in softmax)
// grid: (16, HEADS) — each block handles 100 queries x 2 batches for one head.
__global__ void cross_attn_kernel(const float* __restrict__ Q, const float* __restrict__ KV,
                                  float* __restrict__ out) {
    __shared__ float Kt[2][32][100];   // [b][d][j]
    __shared__ float Vs[2][100][32];   // [b][j][d]
    const int hc = blockIdx.y * 32;
    const int i0 = blockIdx.x * 100;
    const int tid = threadIdx.x;

    for (int idx = tid; idx < 2 * 32 * 100; idx += 256) {
        int j = idx % 100; int t = idx / 100; int d = t & 31; int b = t >> 5;
        Kt[b][d][j] = KV[(size_t)(j * 2 + b) * 512 + hc + d];
    }
    for (int idx = tid; idx < 2 * 100 * 32; idx += 256) {
        int d = idx & 31; int t = idx >> 5; int j = t % 100; int b = t / 100;
        Vs[b][j][d] = KV[(size_t)(j * 2 + b) * 512 + 256 + hc + d];
    }
    __syncthreads();

    const int w = tid >> 5, lane = tid & 31;
    const float scale = 0.17677669529663687f;

    for (int p = w; p < 200; p += 8) {
        int li = p >> 1, b = p & 1;
        int i = i0 + li;
        float q = Q[(size_t)(i * 2 + b) * 256 + hc + lane];
        float s0 = 0.f, s1 = 0.f, s2 = 0.f, s3 = 0.f;
#pragma unroll
        for (int d = 0; d < 32; d++) {
            float qd = __shfl_sync(0xffffffffu, q, d);
            s0 += qd * Kt[b][d][lane];
            s1 += qd * Kt[b][d][lane + 32];
            s2 += qd * Kt[b][d][lane + 64];
            if (lane < 4) s3 += qd * Kt[b][d][lane + 96];
        }
        s0 *= scale; s1 *= scale; s2 *= scale;
        s3 = (lane < 4) ? s3 * scale : -1e30f;
        float m = fmaxf(fmaxf(s0, s1), fmaxf(s2, s3));
#pragma unroll
        for (int o = 16; o; o >>= 1) m = fmaxf(m, __shfl_xor_sync(0xffffffffu, m, o));
        float e0 = __expf(s0 - m), e1 = __expf(s1 - m), e2 = __expf(s2 - m);
        float e3 = (lane < 4) ? __expf(s3 - m) : 0.f;
        float sum = e0 + e1 + e2 + e3;
#pragma unroll
        for (int o = 16; o; o >>= 1) sum += __shfl_xor_sync(0xffffffffu, sum, o);
        float inv = 1.0f / sum;
        float a0 = e0 * inv, a1 = e1 * inv, a2 = e2 * inv, a3 = e3 * inv;

        float oa = 0.f;
#pragma unroll
        for (int jj = 0; jj < 32; jj++) {
            float a = __shfl_sync(0xffffffffu, a0, jj);
            oa += a * Vs[b][jj][lane];
        }
#pragma unroll
        for (int jj = 0; jj < 32; jj++) {
            float a = __shfl_sync(0xffffffffu, a1, jj);
            oa += a * Vs[b][32 + jj][lane];
        }
#pragma unroll
        for (int jj = 0; jj < 32; jj++) {
            float a = __shfl_sync(0xffffffffu, a2, jj);
            oa += a * Vs[b][64 + jj][lane];
        }
#pragma unroll
        for (int jj = 0; jj < 4; jj++) {
            float a = __shfl_sync(0xffffffffu, a3, jj);
            oa += a * Vs[b][96 + jj][lane];
        }
        out[(size_t)(i * 2 + b) * 256 + hc + lane] = oa;
    }
}

// ---------------- launch ----------------
extern "C" void kernel_launch(void* const* d_in, const int* in_sizes, int n_in,
                              void* d_out, int out_size) {
    const float* x       = (const float*)d_in[0];
    const float* gat_W   = (const float*)d_in[1];   // [2][4][256][256]
    const float* gat_b   = (const float*)d_in[2];   // [2][4][256]
    // d_in[3] = gat_rel: unused — edge bias is constant over the (batch) softmax axis and cancels exactly
    const float* cross_W = (const float*)d_in[4];   // [4][256][256]
    const float* cross_b = (const float*)d_in[5];   // [4][256]
    const float* ln_g    = (const float*)d_in[6];   // [3][256]
    const float* ln_b    = (const float*)d_in[7];
    float* out = (float*)d_out;

    float *Gn, *Ln, *qkvg, *qkvl, *att, *proj, *gout, *lout, *qc, *kvc, *catt, *cprj;
    cudaGetSymbolAddress((void**)&Gn,   d_Gn);
    cudaGetSymbolAddress((void**)&Ln,   d_Ln);
    cudaGetSymbolAddress((void**)&qkvg, d_qkvg);
    cudaGetSymbolAddress((void**)&qkvl, d_qkvl);
    cudaGetSymbolAddress((void**)&att,  d_att);
    cudaGetSymbolAddress((void**)&proj, d_proj);
    cudaGetSymbolAddress((void**)&gout, d_gout);
    cudaGetSymbolAddress((void**)&lout, d_lout);
    cudaGetSymbolAddress((void**)&qc,   d_qc);
    cudaGetSymbolAddress((void**)&kvc,  d_kvc);
    cudaGetSymbolAddress((void**)&catt, d_catt);
    cudaGetSymbolAddress((void**)&cprj, d_cprj);

    const int W2 = 256 * 256;  // one weight matrix

    // node construction
    pool_kernel<<<MG, 256>>>(x, Gn);
    to_nodes_kernel<<<NL, 256>>>(x, Ln);

    // ---- global GAT ----
    gemm_bias_kernel<<<dim3(12, 4), 256>>>(Gn, gat_W, gat_b, qkvg, MG, 768);
    gat_attn_kernel<<<dim3(4, HEADS), 256>>>(qkvg, att, NG);
    gemm_bias_kernel<<<dim3(4, 4), 256>>>(att, gat_W + 3 * W2, gat_b + 768, proj, MG, 256);
    add_ln_kernel<<<MG, 256>>>(proj, Gn, ln_g, ln_b, gout, 0);

    // ---- local GAT ----
    gemm_bias_kernel<<<dim3(12, 50), 256>>>(Ln, gat_W + 4 * W2, gat_b + 1024, qkvl, ML, 768);
    gat_attn_kernel<<<dim3(50, HEADS), 256>>>(qkvl, att, NL);
    gemm_bias_kernel<<<dim3(4, 50), 256>>>(att, gat_W + 7 * W2, gat_b + 1024 + 768, proj, ML, 256);
    add_ln_kernel<<<ML, 256>>>(proj, Ln, ln_g + 256, ln_b + 256, lout, 0);

    // ---- cross attention (keys deduplicated: use g_out's 100 rows directly) ----
    gemm_bias_kernel<<<dim3(4, 50), 256>>>(lout, cross_W, cross_b, qc, ML, 256);
    gemm_bias_kernel<<<dim3(8, 4), 256>>>(gout, cross_W + W2, cross_b + 256, kvc, MG, 512);
    cross_attn_kernel<<<dim3(16, HEADS), 256>>>(qc, kvc, catt);
    gemm_bias_kernel<<<dim3(4, 50), 256>>>(catt, cross_W + 3 * W2, cross_b + 768, cprj, ML, 256);
    add_ln_kernel<<<ML, 256>>>(cprj, lout, ln_g + 512, ln_b + 512, out, 1);
}

// round 3
// speedup vs baseline: 1.3441x; 1.3441x over previous
#include <cuda_runtime.h>
#include <math.h>

// Problem constants
#define EDIM   256
#define HEADS  8
#define NL     1600   // local nodes (40x40)
#define NG     100    // global nodes (10x10)
#define HW     1600
#define ML     (NL*2) // 3200 rows (node-major, batch interleaved)
#define MG     (NG*2) // 200 rows

// ---------------- scratch ----------------
__device__ float d_Gn  [MG * EDIM];
__device__ float d_Ln  [ML * EDIM];
__device__ float d_qkvg[MG * 768];
__device__ float d_qkvl[ML * 768];
__device__ float d_att [ML * EDIM];
__device__ float d_proj[ML * EDIM];
__device__ float d_gout[MG * EDIM];
__device__ float d_lout[ML * EDIM];
__device__ float d_qc  [ML * EDIM];
__device__ float d_kvc [MG * 512];
__device__ float d_catt[ML * EDIM];
__device__ float d_cprj[ML * EDIM];

// ---------------- pool: 4x4 avg -> global nodes ----------------
__global__ void pool_kernel(const float* __restrict__ x, float* __restrict__ gn) {
    int blk = blockIdx.x;           // 0..199 = p*2+b
    int p = blk >> 1, b = blk & 1;
    int c = threadIdx.x;
    int pr = p / 10, pc = p % 10;
    const float* xb = x + ((size_t)b * EDIM + c) * HW;
    float s = 0.f;
#pragma unroll
    for (int dy = 0; dy < 4; dy++)
#pragma unroll
        for (int dx = 0; dx < 4; dx++)
            s += xb[(pr * 4 + dy) * 40 + pc * 4 + dx];
    gn[(size_t)blk * EDIM + c] = s * (1.0f / 16.0f);
}

// ---------------- x [B,C,HW] -> nodes [(n*2+b), C] ----------------
__global__ void to_nodes_kernel(const float* __restrict__ x, float* __restrict__ ln) {
    int n = blockIdx.x;
    int c = threadIdx.x;
#pragma unroll
    for (int b = 0; b < 2; b++)
        ln[(size_t)(n * 2 + b) * EDIM + c] = x[((size_t)b * EDIM + c) * HW + n];
}

// ---------------- GEMM: C[M,N] = A[M,256] @ W[N,256]^T + bias[N] ----------------
__global__ __launch_bounds__(256)
void gemm_bias_kernel(const float* __restrict__ A, const float* __restrict__ W,
                      const float* __restrict__ bias, float* __restrict__ C,
                      int M, int N) {
    __shared__ __align__(16) float As[16][68];
    __shared__ __align__(16) float Bs[16][68];
    int bm = blockIdx.y * 64, bn = blockIdx.x * 64;
    int tid = threadIdx.x;
    int lr = tid >> 2;          // 0..63
    int lc = (tid & 3) * 4;     // 0,4,8,12
    int tm = (tid & 15) * 4;
    int tn = (tid >> 4) * 4;
    float acc[4][4];
#pragma unroll
    for (int i = 0; i < 4; i++)
#pragma unroll
        for (int j = 0; j < 4; j++) acc[i][j] = 0.f;

    for (int k0 = 0; k0 < 256; k0 += 16) {
        float4 a4 = make_float4(0.f, 0.f, 0.f, 0.f);
        if (bm + lr < M) a4 = *(const float4*)(A + (size_t)(bm + lr) * 256 + k0 + lc);
        As[lc + 0][lr] = a4.x; As[lc + 1][lr] = a4.y; As[lc + 2][lr] = a4.z; As[lc + 3][lr] = a4.w;
        float4 b4 = *(const float4*)(W + (size_t)(bn + lr) * 256 + k0 + lc);
        Bs[lc + 0][lr] = b4.x; Bs[lc + 1][lr] = b4.y; Bs[lc + 2][lr] = b4.z; Bs[lc + 3][lr] = b4.w;
        __syncthreads();
#pragma unroll
        for (int k = 0; k < 16; k++) {
            float4 av = *(const float4*)&As[k][tm];
            float4 bv = *(const float4*)&Bs[k][tn];
            acc[0][0] += av.x * bv.x; acc[0][1] += av.x * bv.y; acc[0][2] += av.x * bv.z; acc[0][3] += av.x * bv.w;
            acc[1][0] += av.y * bv.x; acc[1][1] += av.y * bv.y; acc[1][2] += av.y * bv.z; acc[1][3] += av.y * bv.w;
            acc[2][0] += av.z * bv.x; acc[2][1] += av.z * bv.y; acc[2][2] += av.z * bv.z; acc[2][3] += av.z * bv.w;
            acc[3][0] += av.w * bv.x; acc[3][1] += av.w * bv.y; acc[3][2] += av.w * bv.z; acc[3][3] += av.w * bv.w;
        }
        __syncthreads();
    }
#pragma unroll
    for (int i = 0; i < 4; i++) {
        int row = bm + tm + i;
        if (row < M) {
#pragma unroll
            for (int j = 0; j < 4; j++)
                C[(size_t)row * N + bn + tn + j] = acc[i][j] + bias[bn + tn + j];
        }
    }
}

// ---------------- fused GAT attention (sigmoid-GEMM form) ----------------
// a0[i,j] = sigmoid(scale*(q0_i.k0_j - q1_i.k1_j)); a1 = 1-a0 (2-way batch softmax,
// elementwise in (i,j) -> no normalization over j).
// O0 = A0 @ V0 ; O1 = colsum(V1) - A0 @ V1
// Block: 64 i-rows x one head; loops over 64-wide j tiles. 256 threads, 4x4 reg tiles.
__global__ __launch_bounds__(256)
void gat_attn_fused(const float* __restrict__ qkv, float* __restrict__ out, int N) {
    extern __shared__ float smbuf[];
    float (*Qs)[68] = (float(*)[68])(smbuf);              // [64 ck][64 i]  ck = b*32+d
    float (*Ks)[68] = (float(*)[68])(smbuf + 64 * 68);    // [64 ck][64 j]  (b=1 negated)
    float (*Vs)[68] = (float(*)[68])(smbuf + 2 * 64 * 68);// [64 j][64 col] col = b*32+d
    float (*Am)[68] = (float(*)[68])(smbuf + 3 * 64 * 68);// [64 j][64 i]   a0

    const int i0 = blockIdx.x * 64;
    const int hc = blockIdx.y * 32;
    const int tid = threadIdx.x;
    const float scale = 0.17677669529663687f;  // 1/sqrt(32)

    // load Q tile: Qs[ck][ii]
#pragma unroll
    for (int t = 0; t < 4; t++) {
        int idx = tid + t * 256;
        int ii = idx & 63;
        int dq = idx >> 6;                 // 0..15
        int b = dq >> 3, d4 = (dq & 7) * 4;
        float4 v = make_float4(0.f, 0.f, 0.f, 0.f);
        if (i0 + ii < N) v = *(const float4*)(qkv + (size_t)((i0 + ii) * 2 + b) * 768 + hc + d4);
        int ck = b * 32 + d4;
        Qs[ck + 0][ii] = v.x; Qs[ck + 1][ii] = v.y; Qs[ck + 2][ii] = v.z; Qs[ck + 3][ii] = v.w;
    }

    const int tm = (tid & 15) * 4;   // i offset
    const int tn = (tid >> 4) * 4;   // j offset (GEMM1) / output col (GEMM2)
    const bool b1 = (tn >= 32);      // warp-uniform

    float o[4][4] = {};
    float vsum[4] = {0.f, 0.f, 0.f, 0.f};

    const int nj = (N + 63) >> 6;
    for (int jt = 0; jt < nj; jt++) {
        const int j0 = jt * 64;
        __syncthreads();   // prev GEMM2 reads done before overwriting K/V
        // load K (b=1 negated) and V tiles
#pragma unroll
        for (int t = 0; t < 4; t++) {
            int idx = tid + t * 256;
            int jj = idx & 63;
            int dq = idx >> 6;
            int b = dq >> 3, d4 = (dq & 7) * 4;
            float4 kv = make_float4(0.f, 0.f, 0.f, 0.f);
            float4 vv = make_float4(0.f, 0.f, 0.f, 0.f);
            if (j0 + jj < N) {
                const float* base = qkv + (size_t)((j0 + jj) * 2 + b) * 768 + hc;
                kv = *(const float4*)(base + 256 + d4);
                vv = *(const float4*)(base + 512 + d4);
            }
            if (b) { kv.x = -kv.x; kv.y = -kv.y; kv.z = -kv.z; kv.w = -kv.w; }
            int ck = b * 32 + d4;
            Ks[ck + 0][jj] = kv.x; Ks[ck + 1][jj] = kv.y; Ks[ck + 2][jj] = kv.z; Ks[ck + 3][jj] = kv.w;
            *(float4*)&Vs[jj][ck] = vv;
        }
        __syncthreads();

        // GEMM1: S[i][j] = sum_ck Qs[ck][i]*Ks[ck][j]  (= q0k0 - q1k1)
        float s[4][4] = {};
#pragma unroll 16
        for (int k = 0; k < 64; k++) {
            float4 a4 = *(const float4*)&Qs[k][tm];
            float4 b4 = *(const float4*)&Ks[k][tn];
            s[0][0] += a4.x * b4.x; s[0][1] += a4.x * b4.y; s[0][2] += a4.x * b4.z; s[0][3] += a4.x * b4.w;
            s[1][0] += a4.y * b4.x; s[1][1] += a4.y * b4.y; s[1][2] += a4.y * b4.z; s[1][3] += a4.y * b4.w;
            s[2][0] += a4.z * b4.x; s[2][1] += a4.z * b4.y; s[2][2] += a4.z * b4.z; s[2][3] += a4.z * b4.w;
            s[3][0] += a4.w * b4.x; s[3][1] += a4.w * b4.y; s[3][2] += a4.w * b4.z; s[3][3] += a4.w * b4.w;
        }
        // sigmoid -> Am[j][i]
#pragma unroll
        for (int jj = 0; jj < 4; jj++) {
            float4 a;
            a.x = 1.f / (1.f + __expf(-scale * s[0][jj]));
            a.y = 1.f / (1.f + __expf(-scale * s[1][jj]));
            a.z = 1.f / (1.f + __expf(-scale * s[2][jj]));
            a.w = 1.f / (1.f + __expf(-scale * s[3][jj]));
            *(float4*)&Am[tn + jj][tm] = a;
        }
        __syncthreads();

        // GEMM2: batch0 cols: O += A @ V0 ; batch1 cols: O -= A @ V1, vsum += V1
        if (!b1) {
#pragma unroll 16
            for (int j = 0; j < 64; j++) {
                float4 a4 = *(const float4*)&Am[j][tm];
                float4 v4 = *(const float4*)&Vs[j][tn];
                o[0][0] += a4.x * v4.x; o[0][1] += a4.x * v4.y; o[0][2] += a4.x * v4.z; o[0][3] += a4.x * v4.w;
                o[1][0] += a4.y * v4.x; o[1][1] += a4.y * v4.y; o[1][2] += a4.y * v4.z; o[1][3] += a4.y * v4.w;
                o[2][0] += a4.z * v4.x; o[2][1] += a4.z * v4.y; o[2][2] += a4.z * v4.z; o[2][3] += a4.z * v4.w;
                o[3][0] += a4.w * v4.x; o[3][1] += a4.w * v4.y; o[3][2] += a4.w * v4.z; o[3][3] += a4.w * v4.w;
            }
        } else {
#pragma unroll 16
            for (int j = 0; j < 64; j++) {
                float4 a4 = *(const float4*)&Am[j][tm];
                float4 v4 = *(const float4*)&Vs[j][tn];
                vsum[0] += v4.x; vsum[1] += v4.y; vsum[2] += v4.z; vsum[3] += v4.w;
                o[0][0] -= a4.x * v4.x; o[0][1] -= a4.x * v4.y; o[0][2] -= a4.x * v4.z; o[0][3] -= a4.x * v4.w;
                o[1][0] -= a4.y * v4.x; o[1][1] -= a4.y * v4.y; o[1][2] -= a4.y * v4.z; o[1][3] -= a4.y * v4.w;
                o[2][0] -= a4.z * v4.x; o[2][1] -= a4.z * v4.y; o[2][2] -= a4.z * v4.z; o[2][3] -= a4.z * v4.w;
                o[3][0] -= a4.w * v4.x; o[3][1] -= a4.w * v4.y; o[3][2] -= a4.w * v4.z; o[3][3] -= a4.w * v4.w;
            }
        }
    }

    // write out: col group tn -> batch b1, dim d
    const int b = b1 ? 1 : 0;
    const int d = tn & 31;
    const float add0 = b1 ? vsum[0] : 0.f, add1 = b1 ? vsum[1] : 0.f;
    const float add2 = b1 ? vsum[2] : 0.f, add3 = b1 ? vsum[3] : 0.f;
#pragma unroll
    for (int ii = 0; ii < 4; ii++) {
        int i = i0 + tm + ii;
        if (i < N) {
            float4 w;
            w.x = o[ii][0] + add0; w.y = o[ii][1] + add1;
            w.z = o[ii][2] + add2; w.w = o[ii][3] + add3;
            *(float4*)(out + (size_t)(i * 2 + b) * 256 + hc + d) = w;
        }
    }
}

// ---------------- residual add + LayerNorm (row-major out) ----------------
__global__ void add_ln_kernel(const float* __restrict__ y, const float* __restrict__ res,
                              const float* __restrict__ g, const float* __restrict__ bt,
                              float* __restrict__ out) {
    int row = blockIdx.x;
    int c = threadIdx.x;
    float v = y[(size_t)row * 256 + c] + res[(size_t)row * 256 + c];

    float s = v, s2 = v * v;
#pragma unroll
    for (int o = 16; o; o >>= 1) {
        s  += __shfl_xor_sync(0xffffffffu, s,  o);
        s2 += __shfl_xor_sync(0xffffffffu, s2, o);
    }
    __shared__ float ws[8], ws2[8];
    int w = c >> 5, l = c & 31;
    if (l == 0) { ws[w] = s; ws2[w] = s2; }
    __syncthreads();
    if (w == 0) {
        float a  = (l < 8) ? ws[l]  : 0.f;
        float a2 = (l < 8) ? ws2[l] : 0.f;
#pragma unroll
        for (int o = 4; o; o >>= 1) {
            a  += __shfl_xor_sync(0xffffffffu, a,  o);
            a2 += __shfl_xor_sync(0xffffffffu, a2, o);
        }
        if (l == 0) { ws[0] = a; ws2[0] = a2; }
    }
    __syncthreads();
    float mean = ws[0] * (1.f / 256.f);
    float var  = ws2[0] * (1.f / 256.f) - mean * mean;
    float rs = rsqrtf(var + 1e-5f);
    out[(size_t)row * 256 + c] = (v - mean) * rs * g[c] + bt[c];
}

// ---------------- final: residual add + LN + transpose to [B,C,HW] ----------------
// block: 8 n-values (16 rows), 512 threads (16 warps, 1 warp per row).
__global__ __launch_bounds__(512)
void add_ln_tr_kernel(const float* __restrict__ y, const float* __restrict__ res,
                      const float* __restrict__ g, const float* __restrict__ bt,
                      float* __restrict__ out) {
    __shared__ float sm[16][260];
    int w = threadIdx.x >> 5, lane = threadIdx.x & 31;
    int row = blockIdx.x * 16 + w;   // row = n*2+b
    float v[8];
    float s = 0.f, s2 = 0.f;
#pragma unroll
    for (int q = 0; q < 8; q++) {
        float t = y[(size_t)row * 256 + q * 32 + lane] + res[(size_t)row * 256 + q * 32 + lane];
        v[q] = t; s += t; s2 += t * t;
    }
#pragma unroll
    for (int o = 16; o; o >>= 1) {
        s  += __shfl_xor_sync(0xffffffffu, s,  o);
        s2 += __shfl_xor_sync(0xffffffffu, s2, o);
    }
    float mean = s * (1.f / 256.f);
    float var  = s2 * (1.f / 256.f) - mean * mean;
    float rs = rsqrtf(var + 1e-5f);
#pragma unroll
    for (int q = 0; q < 8; q++) {
        int c = q * 32 + lane;
        sm[w][c] = (v[q] - mean) * rs * g[c] + bt[c];
    }
    __syncthreads();
    // transposed write: out[(b*256+c)*1600 + n0 + nn], 8 consecutive n per (b,c) = full 32B sectors
    int n0 = blockIdx.x * 8;
    int p = threadIdx.x;             // 0..511
    int b = p >> 8, c = p & 255;
    float4 w0, w1;
    w0.x = sm[0  + b][c]; w0.y = sm[2  + b][c]; w0.z = sm[4  + b][c]; w0.w = sm[6  + b][c];
    w1.x = sm[8  + b][c]; w1.y = sm[10 + b][c]; w1.z = sm[12 + b][c]; w1.w = sm[14 + b][c];
    size_t off = ((size_t)b * 256 + c) * (size_t)HW + n0;
    *(float4*)(out + off)     = w0;
    *(float4*)(out + off + 4) = w1;
}

// ---------------- cross attention: Q[3200 rows], K/V from 100 distinct g_out rows ----------------
__global__ void cross_attn_kernel(const float* __restrict__ Q, const float* __restrict__ KV,
                                  float* __restrict__ out) {
    __shared__ float Kt[2][32][100];   // [b][d][j]
    __shared__ float Vs[2][100][32];   // [b][j][d]
    const int hc = blockIdx.y * 32;
    const int i0 = blockIdx.x * 100;
    const int tid = threadIdx.x;

    for (int idx = tid; idx < 2 * 32 * 100; idx += 256) {
        int j = idx % 100; int t = idx / 100; int d = t & 31; int b = t >> 5;
        Kt[b][d][j] = KV[(size_t)(j * 2 + b) * 512 + hc + d];
    }
    for (int idx = tid; idx < 2 * 100 * 32; idx += 256) {
        int d = idx & 31; int t = idx >> 5; int j = t % 100; int b = t / 100;
        Vs[b][j][d] = KV[(size_t)(j * 2 + b) * 512 + 256 + hc + d];
    }
    __syncthreads();

    const int w = tid >> 5, lane = tid & 31;
    const float scale = 0.17677669529663687f;

    for (int p = w; p < 200; p += 8) {
        int li = p >> 1, b = p & 1;
        int i = i0 + li;
        float q = Q[(size_t)(i * 2 + b) * 256 + hc + lane];
        float s0 = 0.f, s1 = 0.f, s2 = 0.f, s3 = 0.f;
#pragma unroll
        for (int d = 0; d < 32; d++) {
            float qd = __shfl_sync(0xffffffffu, q, d);
            s0 += qd * Kt[b][d][lane];
            s1 += qd * Kt[b][d][lane + 32];
            s2 += qd * Kt[b][d][lane + 64];
            if (lane < 4) s3 += qd * Kt[b][d][lane + 96];
        }
        s0 *= scale; s1 *= scale; s2 *= scale;
        s3 = (lane < 4) ? s3 * scale : -1e30f;
        float m = fmaxf(fmaxf(s0, s1), fmaxf(s2, s3));
#pragma unroll
        for (int o = 16; o; o >>= 1) m = fmaxf(m, __shfl_xor_sync(0xffffffffu, m, o));
        float e0 = __expf(s0 - m), e1 = __expf(s1 - m), e2 = __expf(s2 - m);
        float e3 = (lane < 4) ? __expf(s3 - m) : 0.f;
        float sum = e0 + e1 + e2 + e3;
#pragma unroll
        for (int o = 16; o; o >>= 1) sum += __shfl_xor_sync(0xffffffffu, sum, o);
        float inv = 1.0f / sum;
        float a0 = e0 * inv, a1 = e1 * inv, a2 = e2 * inv, a3 = e3 * inv;

        float oa = 0.f;
#pragma unroll
        for (int jj = 0; jj < 32; jj++) {
            float a = __shfl_sync(0xffffffffu, a0, jj);
            oa += a * Vs[b][jj][lane];
        }
#pragma unroll
        for (int jj = 0; jj < 32; jj++) {
            float a = __shfl_sync(0xffffffffu, a1, jj);
            oa += a * Vs[b][32 + jj][lane];
        }
#pragma unroll
        for (int jj = 0; jj < 32; jj++) {
            float a = __shfl_sync(0xffffffffu, a2, jj);
            oa += a * Vs[b][64 + jj][lane];
        }
#pragma unroll
        for (int jj = 0; jj < 4; jj++) {
            float a = __shfl_sync(0xffffffffu, a3, jj);
            oa += a * Vs[b][96 + jj][lane];
        }
        out[(size_t)(i * 2 + b) * 256 + hc + lane] = oa;
    }
}

// ---------------- launch ----------------
extern "C" void kernel_launch(void* const* d_in, const int* in_sizes, int n_in,
                              void* d_out, int out_size) {
    const float* x       = (const float*)d_in[0];
    const float* gat_W   = (const float*)d_in[1];   // [2][4][256][256]
    const float* gat_b   = (const float*)d_in[2];   // [2][4][256]
    // d_in[3] = gat_rel: edge bias is constant over the batch softmax axis -> cancels exactly
    const float* cross_W = (const float*)d_in[4];   // [4][256][256]
    const float* cross_b = (const float*)d_in[5];   // [4][256]
    const float* ln_g    = (const float*)d_in[6];   // [3][256]
    const float* ln_b    = (const float*)d_in[7];
    float* out = (float*)d_out;

    float *Gn, *Ln, *qkvg, *qkvl, *att, *proj, *gout, *lout, *qc, *kvc, *catt, *cprj;
    cudaGetSymbolAddress((void**)&Gn,   d_Gn);
    cudaGetSymbolAddress((void**)&Ln,   d_Ln);
    cudaGetSymbolAddress((void**)&qkvg, d_qkvg);
    cudaGetSymbolAddress((void**)&qkvl, d_qkvl);
    cudaGetSymbolAddress((void**)&att,  d_att);
    cudaGetSymbolAddress((void**)&proj, d_proj);
    cudaGetSymbolAddress((void**)&gout, d_gout);
    cudaGetSymbolAddress((void**)&lout, d_lout);
    cudaGetSymbolAddress((void**)&qc,   d_qc);
    cudaGetSymbolAddress((void**)&kvc,  d_kvc);
    cudaGetSymbolAddress((void**)&catt, d_catt);
    cudaGetSymbolAddress((void**)&cprj, d_cprj);

    const int W2 = 256 * 256;
    const int ATTN_SMEM = 4 * 64 * 68 * 4;   // 69632 bytes
    cudaFuncSetAttribute(gat_attn_fused, cudaFuncAttributeMaxDynamicSharedMemorySize, ATTN_SMEM);

    // node construction
    pool_kernel<<<MG, 256>>>(x, Gn);
    to_nodes_kernel<<<NL, 256>>>(x, Ln);

    // ---- global GAT ----
    gemm_bias_kernel<<<dim3(12, 4), 256>>>(Gn, gat_W, gat_b, qkvg, MG, 768);
    gat_attn_fused<<<dim3(2, HEADS), 256, ATTN_SMEM>>>(qkvg, att, NG);
    gemm_bias_kernel<<<dim3(4, 4), 256>>>(att, gat_W + 3 * W2, gat_b + 768, proj, MG, 256);
    add_ln_kernel<<<MG, 256>>>(proj, Gn, ln_g, ln_b, gout);

    // ---- local GAT ----
    gemm_bias_kernel<<<dim3(12, 50), 256>>>(Ln, gat_W + 4 * W2, gat_b + 1024, qkvl, ML, 768);
    gat_attn_fused<<<dim3(25, HEADS), 256, ATTN_SMEM>>>(qkvl, att, NL);
    gemm_bias_kernel<<<dim3(4, 50), 256>>>(att, gat_W + 7 * W2, gat_b + 1024 + 768, proj, ML, 256);
    add_ln_kernel<<<ML, 256>>>(proj, Ln, ln_g + 256, ln_b + 256, lout);

    // ---- cross attention (keys deduplicated: 16x upsample cancels in softmax) ----
    gemm_bias_kernel<<<dim3(4, 50), 256>>>(lout, cross_W, cross_b, qc, ML, 256);
    gemm_bias_kernel<<<dim3(8, 4), 256>>>(gout, cross_W + W2, cross_b + 256, kvc, MG, 512);
    cross_attn_kernel<<<dim3(16, HEADS), 256>>>(qc, kvc, catt);
    gemm_bias_kernel<<<dim3(4, 50), 256>>>(catt, cross_W + 3 * W2, cross_b + 768, cprj, ML, 256);
    add_ln_tr_kernel<<<200, 512>>>(cprj, lout, ln_g + 512, ln_b + 512, out);
}

// round 6
// speedup vs baseline: 1.8703x; 1.3915x over previous
#include <cuda_runtime.h>
#include <math.h>

// Problem constants
#define EDIM   256
#define HEADS  8
#define NL     1600   // local nodes (40x40)
#define NG     100    // global nodes (10x10)
#define HW     1600
#define ML     (NL*2) // 3200 rows (node-major, batch interleaved)
#define MG     (NG*2) // 200 rows

// ---------------- scratch ----------------
__device__ float d_Gn   [MG * EDIM];
__device__ float d_Ln   [ML * EDIM];
__device__ float d_qkvg [MG * 768];
__device__ float d_qkvl [ML * 768];
__device__ float d_att  [ML * EDIM];
__device__ float d_attg [MG * EDIM];
__device__ float d_proj [ML * EDIM];
__device__ float d_projg[MG * EDIM];
__device__ float d_gout [MG * EDIM];
__device__ float d_lout [ML * EDIM];
__device__ float d_qc   [ML * EDIM];
__device__ float d_kvc  [MG * 512];
__device__ float d_catt [ML * EDIM];
__device__ float d_cprj [ML * EDIM];

// ---------------- helpers ----------------
__device__ __forceinline__ float tf32r(float x) {
    unsigned u;
    asm("cvt.rna.tf32.f32 %0, %1;" : "=r"(u) : "f"(x));
    return __uint_as_float(u);
}
__device__ __forceinline__ unsigned f2u(float x) { return __float_as_uint(x); }

__device__ __forceinline__ void mma_tf32(float c[4],
    unsigned a0, unsigned a1, unsigned a2, unsigned a3,
    unsigned b0, unsigned b1) {
    asm volatile(
        "mma.sync.aligned.m16n8k8.row.col.f32.tf32.tf32.f32 "
        "{%0,%1,%2,%3}, {%4,%5,%6,%7}, {%8,%9}, {%0,%1,%2,%3};"
        : "+f"(c[0]), "+f"(c[1]), "+f"(c[2]), "+f"(c[3])
        : "r"(a0), "r"(a1), "r"(a2), "r"(a3), "r"(b0), "r"(b1));
}

// ---------------- prep: pool (blocks 0..199) + transpose to nodes (200..1799) ----------------
__global__ void prep_kernel(const float* __restrict__ x, float* __restrict__ gn,
                            float* __restrict__ ln) {
    int blk = blockIdx.x;
    int c = threadIdx.x;
    if (blk < 200) {
        int p = blk >> 1, b = blk & 1;
        int pr = p / 10, pc = p % 10;
        const float* xb = x + ((size_t)b * EDIM + c) * HW;
        float s = 0.f;
#pragma unroll
        for (int dy = 0; dy < 4; dy++)
#pragma unroll
            for (int dx = 0; dx < 4; dx++)
                s += xb[(pr * 4 + dy) * 40 + pc * 4 + dx];
        gn[(size_t)blk * EDIM + c] = s * (1.0f / 16.0f);
    } else {
        int n = blk - 200;
#pragma unroll
        for (int b = 0; b < 2; b++)
            ln[(size_t)(n * 2 + b) * EDIM + c] = x[((size_t)b * EDIM + c) * HW + n];
    }
}

// ---------------- GEMM body (64x64 tile, K=256, 4x4 reg tiles) ----------------
__device__ __forceinline__ void gemm_body(const float* __restrict__ A, const float* __restrict__ Wm,
                                          const float* __restrict__ bias, float* __restrict__ C,
                                          int M, int N, int bm, int bn) {
    __shared__ __align__(16) float As[16][68];
    __shared__ __align__(16) float Bs[16][68];
    int tid = threadIdx.x;
    int lr = tid >> 2;
    int lc = (tid & 3) * 4;
    int tm = (tid & 15) * 4;
    int tn = (tid >> 4) * 4;
    float acc[4][4];
#pragma unroll
    for (int i = 0; i < 4; i++)
#pragma unroll
        for (int j = 0; j < 4; j++) acc[i][j] = 0.f;

    for (int k0 = 0; k0 < 256; k0 += 16) {
        float4 a4 = make_float4(0.f, 0.f, 0.f, 0.f);
        if (bm + lr < M) a4 = *(const float4*)(A + (size_t)(bm + lr) * 256 + k0 + lc);
        As[lc + 0][lr] = a4.x; As[lc + 1][lr] = a4.y; As[lc + 2][lr] = a4.z; As[lc + 3][lr] = a4.w;
        float4 b4 = *(const float4*)(Wm + (size_t)(bn + lr) * 256 + k0 + lc);
        Bs[lc + 0][lr] = b4.x; Bs[lc + 1][lr] = b4.y; Bs[lc + 2][lr] = b4.z; Bs[lc + 3][lr] = b4.w;
        __syncthreads();
#pragma unroll
        for (int k = 0; k < 16; k++) {
            float4 av = *(const float4*)&As[k][tm];
            float4 bv = *(const float4*)&Bs[k][tn];
            acc[0][0] += av.x * bv.x; acc[0][1] += av.x * bv.y; acc[0][2] += av.x * bv.z; acc[0][3] += av.x * bv.w;
            acc[1][0] += av.y * bv.x; acc[1][1] += av.y * bv.y; acc[1][2] += av.y * bv.z; acc[1][3] += av.y * bv.w;
            acc[2][0] += av.z * bv.x; acc[2][1] += av.z * bv.y; acc[2][2] += av.z * bv.z; acc[2][3] += av.z * bv.w;
            acc[3][0] += av.w * bv.x; acc[3][1] += av.w * bv.y; acc[3][2] += av.w * bv.z; acc[3][3] += av.w * bv.w;
        }
        __syncthreads();
    }
#pragma unroll
    for (int i = 0; i < 4; i++) {
        int row = bm + tm + i;
        if (row < M) {
#pragma unroll
            for (int j = 0; j < 4; j++)
                C[(size_t)row * N + bn + tn + j] = acc[i][j] + bias[bn + tn + j];
        }
    }
}

__global__ __launch_bounds__(256)
void gemm_bias_kernel(const float* __restrict__ A, const float* __restrict__ W,
                      const float* __restrict__ bias, float* __restrict__ C, int M, int N) {
    gemm_body(A, W, bias, C, M, N, blockIdx.y * 64, blockIdx.x * 64);
}

// dual GEMM: y < ySplit -> set0, else set1 (blocks with bn >= N early-exit)
__global__ __launch_bounds__(256)
void gemm_dual_kernel(const float* A0, const float* W0, const float* B0, float* C0, int M0, int N0,
                      const float* A1, const float* W1, const float* B1, float* C1, int M1, int N1,
                      int ySplit) {
    const float* A; const float* Wm; const float* bias; float* C; int M, N, by;
    if ((int)blockIdx.y < ySplit) { A = A0; Wm = W0; bias = B0; C = C0; M = M0; N = N0; by = blockIdx.y; }
    else { A = A1; Wm = W1; bias = B1; C = C1; M = M1; N = N1; by = blockIdx.y - ySplit; }
    int bn = blockIdx.x * 64;
    if (bn >= N) return;
    gemm_body(A, Wm, bias, C, M, N, by * 64, bn);
}

// ---------------- tf32 MMA GAT attention ----------------
// a0[i,j] = sigmoid(scale*(q0_i.k0_j - q1_i.k1_j));  O0 = A0@V0 ; O1 = (1-A0)@V1 (masked)
// Block: 64 i-rows, one head. 8 warps. GEMM1: warp (w&3)->i strip, (w>>2)->j half.
// GEMM2: warp (w&3)->i strip, (w>>2)->batch (d half).
__global__ __launch_bounds__(256)
void gat_attn_mma(const float* __restrict__ qkvL, float* __restrict__ outL,
                  const float* __restrict__ qkvG, float* __restrict__ outG) {
    extern __shared__ float sm[];
    float* Qs = sm;                    // [64][68]  Qcat row-major [i][ck]
    float* Ks = sm + 64 * 68;          // [64][68]  Kcat row-major [j][ck] (b=1 negated)
    float* Am = sm + 2 * 64 * 68;      // [64][68]  a0 [i][j]
    float* Vs = sm + 3 * 64 * 68;      // [64][76]  V [j][ck]

    const float* qkv; float* out; int N, i0;
    if (blockIdx.x < 25) { qkv = qkvL; out = outL; N = NL; i0 = blockIdx.x * 64; }
    else                 { qkv = qkvG; out = outG; N = NG; i0 = (blockIdx.x - 25) * 64; }
    const int hc = blockIdx.y * 32;
    const int tid = threadIdx.x;
    const int w = tid >> 5, lane = tid & 31;
    const int r = lane >> 2, c = lane & 3;
    const float scale = 0.17677669529663687f;  // 1/sqrt(32)

    // load Q tile (tf32-rounded)
#pragma unroll
    for (int t = 0; t < 4; t++) {
        int idx = tid + t * 256;
        int ii = idx & 63, dq = idx >> 6;
        int b = dq >> 3, d4 = (dq & 7) * 4;
        float4 v = make_float4(0.f, 0.f, 0.f, 0.f);
        if (i0 + ii < N) v = *(const float4*)(qkv + (size_t)((i0 + ii) * 2 + b) * 768 + hc + d4);
        float* dst = Qs + ii * 68 + b * 32 + d4;
        dst[0] = tf32r(v.x); dst[1] = tf32r(v.y); dst[2] = tf32r(v.z); dst[3] = tf32r(v.w);
    }

    const int ib = (w & 3) * 16;
    const int jb = (w >> 2) * 32;    // GEMM1 j half
    const int batch = w >> 2;        // GEMM2 batch / d half
    float o[4][4];
#pragma unroll
    for (int dn = 0; dn < 4; dn++)
#pragma unroll
        for (int q = 0; q < 4; q++) o[dn][q] = 0.f;

    for (int j0 = 0; j0 < N; j0 += 64) {
        __syncthreads();   // prev-iter reads of Ks/Vs/Am done (also orders Q writes on iter 0)
        // load K (b=1 negated) and V tiles
#pragma unroll
        for (int t = 0; t < 4; t++) {
            int idx = tid + t * 256;
            int jj = idx & 63, dq = idx >> 6;
            int b = dq >> 3, d4 = (dq & 7) * 4;
            float4 kv = make_float4(0.f, 0.f, 0.f, 0.f);
            float4 vv = make_float4(0.f, 0.f, 0.f, 0.f);
            if (j0 + jj < N) {
                const float* base = qkv + (size_t)((j0 + jj) * 2 + b) * 768 + hc;
                kv = *(const float4*)(base + 256 + d4);
                vv = *(const float4*)(base + 512 + d4);
            }
            if (b) { kv.x = -kv.x; kv.y = -kv.y; kv.z = -kv.z; kv.w = -kv.w; }
            int ck = b * 32 + d4;
            float* dk = Ks + jj * 68 + ck;
            dk[0] = tf32r(kv.x); dk[1] = tf32r(kv.y); dk[2] = tf32r(kv.z); dk[3] = tf32r(kv.w);
            float* dv = Vs + jj * 76 + ck;
            dv[0] = tf32r(vv.x); dv[1] = tf32r(vv.y); dv[2] = tf32r(vv.z); dv[3] = tf32r(vv.w);
        }
        __syncthreads();

        // GEMM1: S[16i x 32j] per warp, K-dim = 64 (concat)
        float s[4][4];
#pragma unroll
        for (int jn = 0; jn < 4; jn++)
#pragma unroll
            for (int q = 0; q < 4; q++) s[jn][q] = 0.f;
#pragma unroll
        for (int kk = 0; kk < 64; kk += 8) {
            unsigned a0 = f2u(Qs[(ib + r) * 68 + kk + c]);
            unsigned a1 = f2u(Qs[(ib + r + 8) * 68 + kk + c]);
            unsigned a2 = f2u(Qs[(ib + r) * 68 + kk + 4 + c]);
            unsigned a3 = f2u(Qs[(ib + r + 8) * 68 + kk + 4 + c]);
#pragma unroll
            for (int jn = 0; jn < 4; jn++) {
                const float* kb = Ks + (jb + jn * 8 + r) * 68 + kk;
                mma_tf32(s[jn], a0, a1, a2, a3, f2u(kb[c]), f2u(kb[4 + c]));
            }
        }
        // sigmoid + validity mask -> Am (tf32)
#pragma unroll
        for (int jn = 0; jn < 4; jn++) {
            int jc = jb + jn * 8 + 2 * c;
            bool valid = (j0 + jc) < N;   // pair-uniform (N even)
            float a00 = valid ? 1.f / (1.f + __expf(-scale * s[jn][0])) : 0.f;
            float a01 = valid ? 1.f / (1.f + __expf(-scale * s[jn][1])) : 0.f;
            float a10 = valid ? 1.f / (1.f + __expf(-scale * s[jn][2])) : 0.f;
            float a11 = valid ? 1.f / (1.f + __expf(-scale * s[jn][3])) : 0.f;
            *(float2*)(Am + (ib + r) * 68 + jc)     = make_float2(tf32r(a00), tf32r(a01));
            *(float2*)(Am + (ib + r + 8) * 68 + jc) = make_float2(tf32r(a10), tf32r(a11));
        }
        __syncthreads();

        // GEMM2: O[16i x 32d] per warp; batch0 uses A, batch1 uses (1-A) masked
#pragma unroll
        for (int kk = 0; kk < 64; kk += 8) {
            float f0 = Am[(ib + r) * 68 + kk + c];
            float f1 = Am[(ib + r + 8) * 68 + kk + c];
            float f2 = Am[(ib + r) * 68 + kk + 4 + c];
            float f3 = Am[(ib + r + 8) * 68 + kk + 4 + c];
            if (batch) {
                bool v0 = (j0 + kk + c) < N;
                bool v1 = (j0 + kk + 4 + c) < N;
                f0 = v0 ? tf32r(1.f - f0) : 0.f;
                f1 = v0 ? tf32r(1.f - f1) : 0.f;
                f2 = v1 ? tf32r(1.f - f2) : 0.f;
                f3 = v1 ? tf32r(1.f - f3) : 0.f;
            }
            unsigned a0 = f2u(f0), a1 = f2u(f1), a2 = f2u(f2), a3 = f2u(f3);
#pragma unroll
            for (int dn = 0; dn < 4; dn++) {
                int d = batch * 32 + dn * 8 + r;
                mma_tf32(o[dn], a0, a1, a2, a3,
                         f2u(Vs[(kk + c) * 76 + d]), f2u(Vs[(kk + 4 + c) * 76 + d]));
            }
        }
    }

    // epilogue: write O strip
#pragma unroll
    for (int dn = 0; dn < 4; dn++) {
        int d = dn * 8 + 2 * c;
        int i = i0 + ib + r;
        if (i < N)
            *(float2*)(out + (size_t)(i * 2 + batch) * 256 + hc + d) = make_float2(o[dn][0], o[dn][1]);
        if (i + 8 < N)
            *(float2*)(out + (size_t)((i + 8) * 2 + batch) * 256 + hc + d) = make_float2(o[dn][2], o[dn][3]);
    }
}

// ---------------- residual add + LayerNorm, dual (local rows then global rows) ----------------
__global__ void add_ln_dual(const float* __restrict__ yL, const float* __restrict__ resL,
                            const float* __restrict__ yG, const float* __restrict__ resG,
                            const float* __restrict__ ln_g, const float* __restrict__ ln_b,
                            float* __restrict__ outL, float* __restrict__ outG) {
    int row = blockIdx.x;
    const float* y; const float* res; const float* g; const float* bt; float* out; int rr;
    if (row < ML) { y = yL; res = resL; g = ln_g + 256; bt = ln_b + 256; out = outL; rr = row; }
    else          { y = yG; res = resG; g = ln_g;       bt = ln_b;       out = outG; rr = row - ML; }
    int c = threadIdx.x;
    float v = y[(size_t)rr * 256 + c] + res[(size_t)rr * 256 + c];

    float s = v, s2 = v * v;
#pragma unroll
    for (int o = 16; o; o >>= 1) {
        s  += __shfl_xor_sync(0xffffffffu, s,  o);
        s2 += __shfl_xor_sync(0xffffffffu, s2, o);
    }
    __shared__ float ws[8], ws2[8];
    int w = c >> 5, l = c & 31;
    if (l == 0) { ws[w] = s; ws2[w] = s2; }
    __syncthreads();
    if (w == 0) {
        float a  = (l < 8) ? ws[l]  : 0.f;
        float a2 = (l < 8) ? ws2[l] : 0.f;
#pragma unroll
        for (int o = 4; o; o >>= 1) {
            a  += __shfl_xor_sync(0xffffffffu, a,  o);
            a2 += __shfl_xor_sync(0xffffffffu, a2, o);
        }
        if (l == 0) { ws[0] = a; ws2[0] = a2; }
    }
    __syncthreads();
    float mean = ws[0] * (1.f / 256.f);
    float var  = ws2[0] * (1.f / 256.f) - mean * mean;
    float rs = rsqrtf(var + 1e-5f);
    out[(size_t)rr * 256 + c] = (v - mean) * rs * g[c] + bt[c];
}

// ---------------- final: residual add + LN + transpose to [B,C,HW] ----------------
__global__ __launch_bounds__(512)
void add_ln_tr_kernel(const float* __restrict__ y, const float* __restrict__ res,
                      const float* __restrict__ g, const float* __restrict__ bt,
                      float* __restrict__ out) {
    __shared__ float smn[16][260];
    int w = threadIdx.x >> 5, lane = threadIdx.x & 31;
    int row = blockIdx.x * 16 + w;
    float v[8];
    float s = 0.f, s2 = 0.f;
#pragma unroll
    for (int q = 0; q < 8; q++) {
        float t = y[(size_t)row * 256 + q * 32 + lane] + res[(size_t)row * 256 + q * 32 + lane];
        v[q] = t; s += t; s2 += t * t;
    }
#pragma unroll
    for (int o = 16; o; o >>= 1) {
        s  += __shfl_xor_sync(0xffffffffu, s,  o);
        s2 += __shfl_xor_sync(0xffffffffu, s2, o);
    }
    float mean = s * (1.f / 256.f);
    float var  = s2 * (1.f / 256.f) - mean * mean;
    float rs = rsqrtf(var + 1e-5f);
#pragma unroll
    for (int q = 0; q < 8; q++) {
        int c = q * 32 + lane;
        smn[w][c] = (v[q] - mean) * rs * g[c] + bt[c];
    }
    __syncthreads();
    int n0 = blockIdx.x * 8;
    int p = threadIdx.x;
    int b = p >> 8, c = p & 255;
    float4 w0, w1;
    w0.x = smn[0 + b][c]; w0.y = smn[2 + b][c]; w0.z = smn[4 + b][c]; w0.w = smn[6 + b][c];
    w1.x = smn[8 + b][c]; w1.y = smn[10 + b][c]; w1.z = smn[12 + b][c]; w1.w = smn[14 + b][c];
    size_t off = ((size_t)b * 256 + c) * (size_t)HW + n0;
    *(float4*)(out + off)     = w0;
    *(float4*)(out + off + 4) = w1;
}

// ---------------- cross attention: Q[3200 rows], K/V from 100 distinct g_out rows ----------------
__global__ void cross_attn_kernel(const float* __restrict__ Q, const float* __restrict__ KV,
                                  float* __restrict__ out) {
    __shared__ float Kt[2][32][100];
    __shared__ float Vs[2][100][32];
    const int hc = blockIdx.y * 32;
    const int i0 = blockIdx.x * 100;
    const int tid = threadIdx.x;

    for (int idx = tid; idx < 2 * 32 * 100; idx += 256) {
        int j = idx % 100; int t = idx / 100; int d = t & 31; int b = t >> 5;
        Kt[b][d][j] = KV[(size_t)(j * 2 + b) * 512 + hc + d];
    }
    for (int idx = tid; idx < 2 * 100 * 32; idx += 256) {
        int d = idx & 31; int t = idx >> 5; int j = t % 100; int b = t / 100;
        Vs[b][j][d] = KV[(size_t)(j * 2 + b) * 512 + 256 + hc + d];
    }
    __syncthreads();

    const int w = tid >> 5, lane = tid & 31;
    const float scale = 0.17677669529663687f;

    for (int p = w; p < 200; p += 8) {
        int li = p >> 1, b = p & 1;
        int i = i0 + li;
        float q = Q[(size_t)(i * 2 + b) * 256 + hc + lane];
        float s0 = 0.f, s1 = 0.f, s2 = 0.f, s3 = 0.f;
#pragma unroll
        for (int d = 0; d < 32; d++) {
            float qd = __shfl_sync(0xffffffffu, q, d);
            s0 += qd * Kt[b][d][lane];
            s1 += qd * Kt[b][d][lane + 32];
            s2 += qd * Kt[b][d][lane + 64];
            if (lane < 4) s3 += qd * Kt[b][d][lane + 96];
        }
        s0 *= scale; s1 *= scale; s2 *= scale;
        s3 = (lane < 4) ? s3 * scale : -1e30f;
        float m = fmaxf(fmaxf(s0, s1), fmaxf(s2, s3));
#pragma unroll
        for (int o = 16; o; o >>= 1) m = fmaxf(m, __shfl_xor_sync(0xffffffffu, m, o));
        float e0 = __expf(s0 - m), e1 = __expf(s1 - m), e2 = __expf(s2 - m);
        float e3 = (lane < 4) ? __expf(s3 - m) : 0.f;
        float sum = e0 + e1 + e2 + e3;
#pragma unroll
        for (int o = 16; o; o >>= 1) sum += __shfl_xor_sync(0xffffffffu, sum, o);
        float inv = 1.0f / sum;
        float a0 = e0 * inv, a1 = e1 * inv, a2 = e2 * inv, a3 = e3 * inv;

        float oa = 0.f;
#pragma unroll
        for (int jj = 0; jj < 32; jj++) {
            float a = __shfl_sync(0xffffffffu, a0, jj);
            oa += a * Vs[b][jj][lane];
        }
#pragma unroll
        for (int jj = 0; jj < 32; jj++) {
            float a = __shfl_sync(0xffffffffu, a1, jj);
            oa += a * Vs[b][32 + jj][lane];
        }
#pragma unroll
        for (int jj = 0; jj < 32; jj++) {
            float a = __shfl_sync(0xffffffffu, a2, jj);
            oa += a * Vs[b][64 + jj][lane];
        }
#pragma unroll
        for (int jj = 0; jj < 4; jj++) {
            float a = __shfl_sync(0xffffffffu, a3, jj);
            oa += a * Vs[b][96 + jj][lane];
        }
        out[(size_t)(i * 2 + b) * 256 + hc + lane] = oa;
    }
}

// ---------------- launch ----------------
extern "C" void kernel_launch(void* const* d_in, const int* in_sizes, int n_in,
                              void* d_out, int out_size) {
    const float* x       = (const float*)d_in[0];
    const float* gat_W   = (const float*)d_in[1];   // [2][4][256][256]
    const float* gat_b   = (const float*)d_in[2];   // [2][4][256]
    // d_in[3] = gat_rel: edge bias constant along batch softmax axis -> cancels exactly
    const float* cross_W = (const float*)d_in[4];
    const float* cross_b = (const float*)d_in[5];
    const float* ln_g    = (const float*)d_in[6];
    const float* ln_b    = (const float*)d_in[7];
    float* out = (float*)d_out;

    float *Gn, *Ln, *qkvg, *qkvl, *att, *attg, *proj, *projg, *gout, *lout, *qc, *kvc, *catt, *cprj;
    cudaGetSymbolAddress((void**)&Gn,    d_Gn);
    cudaGetSymbolAddress((void**)&Ln,    d_Ln);
    cudaGetSymbolAddress((void**)&qkvg,  d_qkvg);
    cudaGetSymbolAddress((void**)&qkvl,  d_qkvl);
    cudaGetSymbolAddress((void**)&att,   d_att);
    cudaGetSymbolAddress((void**)&attg,  d_attg);
    cudaGetSymbolAddress((void**)&proj,  d_proj);
    cudaGetSymbolAddress((void**)&projg, d_projg);
    cudaGetSymbolAddress((void**)&gout,  d_gout);
    cudaGetSymbolAddress((void**)&lout,  d_lout);
    cudaGetSymbolAddress((void**)&qc,    d_qc);
    cudaGetSymbolAddress((void**)&kvc,   d_kvc);
    cudaGetSymbolAddress((void**)&catt,  d_catt);
    cudaGetSymbolAddress((void**)&cprj,  d_cprj);

    const int W2 = 256 * 256;
    const int ATTN_SMEM = (3 * 64 * 68 + 64 * 76) * 4;   // 71680 bytes
    cudaFuncSetAttribute(gat_attn_mma, cudaFuncAttributeMaxDynamicSharedMemorySize, ATTN_SMEM);

    // node construction (pool + transpose merged)
    prep_kernel<<<1800, 256>>>(x, Gn, Ln);

    // qkv projections (local + global merged)
    gemm_dual_kernel<<<dim3(12, 54), 256>>>(
        Ln, gat_W + 4 * W2, gat_b + 1024, qkvl, ML, 768,
        Gn, gat_W,          gat_b,        qkvg, MG, 768, 50);

    // GAT attention (tf32 MMA, local x<25 + global x>=25)
    gat_attn_mma<<<dim3(27, HEADS), 256, ATTN_SMEM>>>(qkvl, att, qkvg, attg);

    // out projections (merged)
    gemm_dual_kernel<<<dim3(4, 54), 256>>>(
        att,  gat_W + 7 * W2, gat_b + 1024 + 768, proj,  ML, 256,
        attg, gat_W + 3 * W2, gat_b + 768,        projg, MG, 256, 50);

    // add + LN (merged)
    add_ln_dual<<<ML + MG, 256>>>(proj, Ln, projg, Gn, ln_g, ln_b, lout, gout);

    // cross projections: Q (local) + KV (global, 100 distinct keys) merged
    gemm_dual_kernel<<<dim3(8, 54), 256>>>(
        lout, cross_W,      cross_b,       qc,  ML, 256,
        gout, cross_W + W2, cross_b + 256, kvc, MG, 512, 50);

    cross_attn_kernel<<<dim3(16, HEADS), 256>>>(qc, kvc, catt);
    gemm_bias_kernel<<<dim3(4, 50), 256>>>(catt, cross_W + 3 * W2, cross_b + 768, cprj, ML, 256);
    add_ln_tr_kernel<<<200, 512>>>(cprj, lout, ln_g + 512, ln_b + 512, out);
}

// round 7
// speedup vs baseline: 2.1455x; 1.1471x over previous
#include <cuda_runtime.h>
#include <math.h>

// Problem constants
#define EDIM   256
#define HEADS  8
#define NL     1600   // local nodes (40x40)
#define NG     100    // global nodes (10x10)
#define HW     1600
#define ML     (NL*2) // 3200 rows (node-major, batch interleaved)
#define MG     (NG*2) // 200 rows

// ---------------- scratch ----------------
__device__ float d_Gn   [MG * EDIM];
__device__ float d_Ln   [ML * EDIM];
__device__ float d_qkvg [MG * 768];
__device__ float d_qkvl [ML * 768];
__device__ float d_att  [ML * EDIM];
__device__ float d_attg [MG * EDIM];
__device__ float d_proj [ML * EDIM];
__device__ float d_projg[MG * EDIM];
__device__ float d_gout [MG * EDIM];
__device__ float d_lout [ML * EDIM];
__device__ float d_qc   [ML * EDIM];
__device__ float d_kvc  [MG * 512];
__device__ float d_catt [ML * EDIM];
__device__ float d_cprj [ML * EDIM];

// ---------------- helpers ----------------
__device__ __forceinline__ float tf32r(float x) {
    unsigned u;
    asm("cvt.rna.tf32.f32 %0, %1;" : "=r"(u) : "f"(x));
    return __uint_as_float(u);
}
__device__ __forceinline__ unsigned f2u(float x) { return __float_as_uint(x); }

__device__ __forceinline__ void mma_tf32(float c[4],
    unsigned a0, unsigned a1, unsigned a2, unsigned a3,
    unsigned b0, unsigned b1) {
    asm volatile(
        "mma.sync.aligned.m16n8k8.row.col.f32.tf32.tf32.f32 "
        "{%0,%1,%2,%3}, {%4,%5,%6,%7}, {%8,%9}, {%0,%1,%2,%3};"
        : "+f"(c[0]), "+f"(c[1]), "+f"(c[2]), "+f"(c[3])
        : "r"(a0), "r"(a1), "r"(a2), "r"(a3), "r"(b0), "r"(b1));
}

// ---------------- prep: pool (blocks 0..199) + transpose to nodes (200..1799) ----------------
__global__ void prep_kernel(const float* __restrict__ x, float* __restrict__ gn,
                            float* __restrict__ ln) {
    int blk = blockIdx.x;
    int c = threadIdx.x;
    if (blk < 200) {
        int p = blk >> 1, b = blk & 1;
        int pr = p / 10, pc = p % 10;
        const float* xb = x + ((size_t)b * EDIM + c) * HW;
        float s = 0.f;
#pragma unroll
        for (int dy = 0; dy < 4; dy++)
#pragma unroll
            for (int dx = 0; dx < 4; dx++)
                s += xb[(pr * 4 + dy) * 40 + pc * 4 + dx];
        gn[(size_t)blk * EDIM + c] = s * (1.0f / 16.0f);
    } else {
        int n = blk - 200;
#pragma unroll
        for (int b = 0; b < 2; b++)
            ln[(size_t)(n * 2 + b) * EDIM + c] = x[((size_t)b * EDIM + c) * HW + n];
    }
}

// ---------------- 3xTF32 tensor GEMM: C[M,N] = A[M,256] @ W[N,256]^T + bias[N] ----------------
// 64x64 tile, 256 threads (8 warps), K chunked by 32.
// Operand split v = hi + lo (hi tf32-rounded); acc += hi*hi + lo*hi + hi*lo  -> ~fp32 accuracy.
__device__ __forceinline__ void gemm_tc_body(const float* __restrict__ A, const float* __restrict__ Wm,
                                             const float* __restrict__ bias, float* __restrict__ C,
                                             int M, int N, int bm, int bn) {
    __shared__ __align__(16) float Ah[64][36];
    __shared__ __align__(16) float Al[64][36];
    __shared__ __align__(16) float Bh[64][36];
    __shared__ __align__(16) float Bl[64][36];

    const int tid = threadIdx.x;
    const int w = tid >> 5, lane = tid & 31;
    const int r = lane >> 2, c = lane & 3;
    const int ms = (w & 3) * 16;     // m strip (16 rows)
    const int ns = (w >> 2) * 32;    // n half (4 subtiles of 8)

    float acc[4][4];
#pragma unroll
    for (int nn = 0; nn < 4; nn++)
#pragma unroll
        for (int q = 0; q < 4; q++) acc[nn][q] = 0.f;

    for (int k0 = 0; k0 < 256; k0 += 32) {
        __syncthreads();
#pragma unroll
        for (int t = 0; t < 2; t++) {
            int idx = tid + t * 256;        // 0..511
            int row = idx >> 3;             // 0..63
            int k4  = (idx & 7) * 4;        // 0..28
            float4 av = make_float4(0.f, 0.f, 0.f, 0.f);
            if (bm + row < M) av = *(const float4*)(A + (size_t)(bm + row) * 256 + k0 + k4);
            float4 ah, al;
            ah.x = tf32r(av.x); al.x = av.x - ah.x;
            ah.y = tf32r(av.y); al.y = av.y - ah.y;
            ah.z = tf32r(av.z); al.z = av.z - ah.z;
            ah.w = tf32r(av.w); al.w = av.w - ah.w;
            *(float4*)&Ah[row][k4] = ah;
            *(float4*)&Al[row][k4] = al;
            float4 bv = *(const float4*)(Wm + (size_t)(bn + row) * 256 + k0 + k4);
            float4 bh, bl;
            bh.x = tf32r(bv.x); bl.x = bv.x - bh.x;
            bh.y = tf32r(bv.y); bl.y = bv.y - bh.y;
            bh.z = tf32r(bv.z); bl.z = bv.z - bh.z;
            bh.w = tf32r(bv.w); bl.w = bv.w - bh.w;
            *(float4*)&Bh[row][k4] = bh;
            *(float4*)&Bl[row][k4] = bl;
        }
        __syncthreads();

#pragma unroll
        for (int kk = 0; kk < 32; kk += 8) {
            unsigned ah0 = f2u(Ah[ms + r][kk + c]);
            unsigned ah1 = f2u(Ah[ms + r + 8][kk + c]);
            unsigned ah2 = f2u(Ah[ms + r][kk + c + 4]);
            unsigned ah3 = f2u(Ah[ms + r + 8][kk + c + 4]);
            unsigned al0 = f2u(Al[ms + r][kk + c]);
            unsigned al1 = f2u(Al[ms + r + 8][kk + c]);
            unsigned al2 = f2u(Al[ms + r][kk + c + 4]);
            unsigned al3 = f2u(Al[ms + r + 8][kk + c + 4]);
#pragma unroll
            for (int nn = 0; nn < 4; nn++) {
                int n = ns + nn * 8 + r;
                unsigned bh0 = f2u(Bh[n][kk + c]), bh1 = f2u(Bh[n][kk + c + 4]);
                unsigned bl0 = f2u(Bl[n][kk + c]), bl1 = f2u(Bl[n][kk + c + 4]);
                mma_tf32(acc[nn], ah0, ah1, ah2, ah3, bh0, bh1);
                mma_tf32(acc[nn], al0, al1, al2, al3, bh0, bh1);
                mma_tf32(acc[nn], ah0, ah1, ah2, ah3, bl0, bl1);
            }
        }
    }

    // epilogue: acc[nn] -> rows (ms+r, ms+r+8), cols (2c, 2c+1) of subtile nn
#pragma unroll
    for (int nn = 0; nn < 4; nn++) {
        int ncol = bn + ns + nn * 8 + 2 * c;
        float2 bb = *(const float2*)(bias + ncol);
        int row = bm + ms + r;
        if (row < M)
            *(float2*)(C + (size_t)row * N + ncol) = make_float2(acc[nn][0] + bb.x, acc[nn][1] + bb.y);
        if (row + 8 < M)
            *(float2*)(C + (size_t)(row + 8) * N + ncol) = make_float2(acc[nn][2] + bb.x, acc[nn][3] + bb.y);
    }
}

__global__ __launch_bounds__(256)
void gemm_bias_kernel(const float* __restrict__ A, const float* __restrict__ W,
                      const float* __restrict__ bias, float* __restrict__ C, int M, int N) {
    gemm_tc_body(A, W, bias, C, M, N, blockIdx.y * 64, blockIdx.x * 64);
}

// dual GEMM: y < ySplit -> set0, else set1 (blocks with bn >= N early-exit)
__global__ __launch_bounds__(256)
void gemm_dual_kernel(const float* A0, const float* W0, const float* B0, float* C0, int M0, int N0,
                      const float* A1, const float* W1, const float* B1, float* C1, int M1, int N1,
                      int ySplit) {
    const float* A; const float* Wm; const float* bias; float* C; int M, N, by;
    if ((int)blockIdx.y < ySplit) { A = A0; Wm = W0; bias = B0; C = C0; M = M0; N = N0; by = blockIdx.y; }
    else { A = A1; Wm = W1; bias = B1; C = C1; M = M1; N = N1; by = blockIdx.y - ySplit; }
    int bn = blockIdx.x * 64;
    if (bn >= N) return;
    gemm_tc_body(A, Wm, bias, C, M, N, by * 64, bn);
}

// ---------------- tf32 MMA GAT attention ----------------
// a0[i,j] = sigmoid(scale*(q0_i.k0_j - q1_i.k1_j));  O0 = A0@V0 ; O1 = (1-A0)@V1 (masked)
__global__ __launch_bounds__(256)
void gat_attn_mma(const float* __restrict__ qkvL, float* __restrict__ outL,
                  const float* __restrict__ qkvG, float* __restrict__ outG) {
    extern __shared__ float sm[];
    float* Qs = sm;                    // [64][68]  Qcat row-major [i][ck]
    float* Ks = sm + 64 * 68;          // [64][68]  Kcat row-major [j][ck] (b=1 negated)
    float* Am = sm + 2 * 64 * 68;      // [64][68]  a0 [i][j]
    float* Vs = sm + 3 * 64 * 68;      // [64][76]  V [j][ck]

    const float* qkv; float* out; int N, i0;
    if (blockIdx.x < 25) { qkv = qkvL; out = outL; N = NL; i0 = blockIdx.x * 64; }
    else                 { qkv = qkvG; out = outG; N = NG; i0 = (blockIdx.x - 25) * 64; }
    const int hc = blockIdx.y * 32;
    const int tid = threadIdx.x;
    const int w = tid >> 5, lane = tid & 31;
    const int r = lane >> 2, c = lane & 3;
    const float scale = 0.17677669529663687f;  // 1/sqrt(32)

    // load Q tile (tf32-rounded)
#pragma unroll
    for (int t = 0; t < 4; t++) {
        int idx = tid + t * 256;
        int ii = idx & 63, dq = idx >> 6;
        int b = dq >> 3, d4 = (dq & 7) * 4;
        float4 v = make_float4(0.f, 0.f, 0.f, 0.f);
        if (i0 + ii < N) v = *(const float4*)(qkv + (size_t)((i0 + ii) * 2 + b) * 768 + hc + d4);
        float* dst = Qs + ii * 68 + b * 32 + d4;
        dst[0] = tf32r(v.x); dst[1] = tf32r(v.y); dst[2] = tf32r(v.z); dst[3] = tf32r(v.w);
    }

    const int ib = (w & 3) * 16;
    const int jb = (w >> 2) * 32;    // GEMM1 j half
    const int batch = w >> 2;        // GEMM2 batch / d half
    float o[4][4];
#pragma unroll
    for (int dn = 0; dn < 4; dn++)
#pragma unroll
        for (int q = 0; q < 4; q++) o[dn][q] = 0.f;

    for (int j0 = 0; j0 < N; j0 += 64) {
        __syncthreads();   // prev-iter reads of Ks/Vs/Am done (also orders Q writes on iter 0)
        // load K (b=1 negated) and V tiles
#pragma unroll
        for (int t = 0; t < 4; t++) {
            int idx = tid + t * 256;
            int jj = idx & 63, dq = idx >> 6;
            int b = dq >> 3, d4 = (dq & 7) * 4;
            float4 kv = make_float4(0.f, 0.f, 0.f, 0.f);
            float4 vv = make_float4(0.f, 0.f, 0.f, 0.f);
            if (j0 + jj < N) {
                const float* base = qkv + (size_t)((j0 + jj) * 2 + b) * 768 + hc;
                kv = *(const float4*)(base + 256 + d4);
                vv = *(const float4*)(base + 512 + d4);
            }
            if (b) { kv.x = -kv.x; kv.y = -kv.y; kv.z = -kv.z; kv.w = -kv.w; }
            int ck = b * 32 + d4;
            float* dk = Ks + jj * 68 + ck;
            dk[0] = tf32r(kv.x); dk[1] = tf32r(kv.y); dk[2] = tf32r(kv.z); dk[3] = tf32r(kv.w);
            float* dv = Vs + jj * 76 + ck;
            dv[0] = tf32r(vv.x); dv[1] = tf32r(vv.y); dv[2] = tf32r(vv.z); dv[3] = tf32r(vv.w);
        }
        __syncthreads();

        // GEMM1: S[16i x 32j] per warp, K-dim = 64 (concat)
        float s[4][4];
#pragma unroll
        for (int jn = 0; jn < 4; jn++)
#pragma unroll
            for (int q = 0; q < 4; q++) s[jn][q] = 0.f;
#pragma unroll
        for (int kk = 0; kk < 64; kk += 8) {
            unsigned a0 = f2u(Qs[(ib + r) * 68 + kk + c]);
            unsigned a1 = f2u(Qs[(ib + r + 8) * 68 + kk + c]);
            unsigned a2 = f2u(Qs[(ib + r) * 68 + kk + 4 + c]);
            unsigned a3 = f2u(Qs[(ib + r + 8) * 68 + kk + 4 + c]);
#pragma unroll
            for (int jn = 0; jn < 4; jn++) {
                const float* kb = Ks + (jb + jn * 8 + r) * 68 + kk;
                mma_tf32(s[jn], a0, a1, a2, a3, f2u(kb[c]), f2u(kb[4 + c]));
            }
        }
        // sigmoid + validity mask -> Am (tf32)
#pragma unroll
        for (int jn = 0; jn < 4; jn++) {
            int jc = jb + jn * 8 + 2 * c;
            bool valid = (j0 + jc) < N;   // pair-uniform (N even)
            float a00 = valid ? 1.f / (1.f + __expf(-scale * s[jn][0])) : 0.f;
            float a01 = valid ? 1.f / (1.f + __expf(-scale * s[jn][1])) : 0.f;
            float a10 = valid ? 1.f / (1.f + __expf(-scale * s[jn][2])) : 0.f;
            float a11 = valid ? 1.f / (1.f + __expf(-scale * s[jn][3])) : 0.f;
            *(float2*)(Am + (ib + r) * 68 + jc)     = make_float2(tf32r(a00), tf32r(a01));
            *(float2*)(Am + (ib + r + 8) * 68 + jc) = make_float2(tf32r(a10), tf32r(a11));
        }
        __syncthreads();

        // GEMM2: O[16i x 32d] per warp; batch0 uses A, batch1 uses (1-A) masked
#pragma unroll
        for (int kk = 0; kk < 64; kk += 8) {
            float f0 = Am[(ib + r) * 68 + kk + c];
            float f1 = Am[(ib + r + 8) * 68 + kk + c];
            float f2 = Am[(ib + r) * 68 + kk + 4 + c];
            float f3 = Am[(ib + r + 8) * 68 + kk + 4 + c];
            if (batch) {
                bool v0 = (j0 + kk + c) < N;
                bool v1 = (j0 + kk + 4 + c) < N;
                f0 = v0 ? tf32r(1.f - f0) : 0.f;
                f1 = v0 ? tf32r(1.f - f1) : 0.f;
                f2 = v1 ? tf32r(1.f - f2) : 0.f;
                f3 = v1 ? tf32r(1.f - f3) : 0.f;
            }
            unsigned a0 = f2u(f0), a1 = f2u(f1), a2 = f2u(f2), a3 = f2u(f3);
#pragma unroll
            for (int dn = 0; dn < 4; dn++) {
                int d = batch * 32 + dn * 8 + r;
                mma_tf32(o[dn], a0, a1, a2, a3,
                         f2u(Vs[(kk + c) * 76 + d]), f2u(Vs[(kk + 4 + c) * 76 + d]));
            }
        }
    }

    // epilogue: write O strip
#pragma unroll
    for (int dn = 0; dn < 4; dn++) {
        int d = dn * 8 + 2 * c;
        int i = i0 + ib + r;
        if (i < N)
            *(float2*)(out + (size_t)(i * 2 + batch) * 256 + hc + d) = make_float2(o[dn][0], o[dn][1]);
        if (i + 8 < N)
            *(float2*)(out + (size_t)((i + 8) * 2 + batch) * 256 + hc + d) = make_float2(o[dn][2], o[dn][3]);
    }
}

// ---------------- residual add + LayerNorm, dual (local rows then global rows) ----------------
__global__ void add_ln_dual(const float* __restrict__ yL, const float* __restrict__ resL,
                            const float* __restrict__ yG, const float* __restrict__ resG,
                            const float* __restrict__ ln_g, const float* __restrict__ ln_b,
                            float* __restrict__ outL, float* __restrict__ outG) {
    int row = blockIdx.x;
    const float* y; const float* res; const float* g; const float* bt; float* out; int rr;
    if (row < ML) { y = yL; res = resL; g = ln_g + 256; bt = ln_b + 256; out = outL; rr = row; }
    else          { y = yG; res = resG; g = ln_g;       bt = ln_b;       out = outG; rr = row - ML; }
    int c = threadIdx.x;
    float v = y[(size_t)rr * 256 + c] + res[(size_t)rr * 256 + c];

    float s = v, s2 = v * v;
#pragma unroll
    for (int o = 16; o; o >>= 1) {
        s  += __shfl_xor_sync(0xffffffffu, s,  o);
        s2 += __shfl_xor_sync(0xffffffffu, s2, o);
    }
    __shared__ float ws[8], ws2[8];
    int w = c >> 5, l = c & 31;
    if (l == 0) { ws[w] = s; ws2[w] = s2; }
    __syncthreads();
    if (w == 0) {
        float a  = (l < 8) ? ws[l]  : 0.f;
        float a2 = (l < 8) ? ws2[l] : 0.f;
#pragma unroll
        for (int o = 4; o; o >>= 1) {
            a  += __shfl_xor_sync(0xffffffffu, a,  o);
            a2 += __shfl_xor_sync(0xffffffffu, a2, o);
        }
        if (l == 0) { ws[0] = a; ws2[0] = a2; }
    }
    __syncthreads();
    float mean = ws[0] * (1.f / 256.f);
    float var  = ws2[0] * (1.f / 256.f) - mean * mean;
    float rs = rsqrtf(var + 1e-5f);
    out[(size_t)rr * 256 + c] = (v - mean) * rs * g[c] + bt[c];
}

// ---------------- final: residual add + LN + transpose to [B,C,HW] ----------------
__global__ __launch_bounds__(512)
void add_ln_tr_kernel(const float* __restrict__ y, const float* __restrict__ res,
                      const float* __restrict__ g, const float* __restrict__ bt,
                      float* __restrict__ out) {
    __shared__ float smn[16][260];
    int w = threadIdx.x >> 5, lane = threadIdx.x & 31;
    int row = blockIdx.x * 16 + w;
    float v[8];
    float s = 0.f, s2 = 0.f;
#pragma unroll
    for (int q = 0; q < 8; q++) {
        float t = y[(size_t)row * 256 + q * 32 + lane] + res[(size_t)row * 256 + q * 32 + lane];
        v[q] = t; s += t; s2 += t * t;
    }
#pragma unroll
    for (int o = 16; o; o >>= 1) {
        s  += __shfl_xor_sync(0xffffffffu, s,  o);
        s2 += __shfl_xor_sync(0xffffffffu, s2, o);
    }
    float mean = s * (1.f / 256.f);
    float var  = s2 * (1.f / 256.f) - mean * mean;
    float rs = rsqrtf(var + 1e-5f);
#pragma unroll
    for (int q = 0; q < 8; q++) {
        int c = q * 32 + lane;
        smn[w][c] = (v[q] - mean) * rs * g[c] + bt[c];
    }
    __syncthreads();
    int n0 = blockIdx.x * 8;
    int p = threadIdx.x;
    int b = p >> 8, c = p & 255;
    float4 w0, w1;
    w0.x = smn[0 + b][c]; w0.y = smn[2 + b][c]; w0.z = smn[4 + b][c]; w0.w = smn[6 + b][c];
    w1.x = smn[8 + b][c]; w1.y = smn[10 + b][c]; w1.z = smn[12 + b][c]; w1.w = smn[14 + b][c];
    size_t off = ((size_t)b * 256 + c) * (size_t)HW + n0;
    *(float4*)(out + off)     = w0;
    *(float4*)(out + off + 4) = w1;
}

// ---------------- cross attention: Q[3200 rows], K/V from 100 distinct g_out rows ----------------
__global__ void cross_attn_kernel(const float* __restrict__ Q, const float* __restrict__ KV,
                                  float* __restrict__ out) {
    __shared__ float Kt[2][32][100];
    __shared__ float Vs[2][100][32];
    const int hc = blockIdx.y * 32;
    const int i0 = blockIdx.x * 100;
    const int tid = threadIdx.x;

    for (int idx = tid; idx < 2 * 32 * 100; idx += 256) {
        int j = idx % 100; int t = idx / 100; int d = t & 31; int b = t >> 5;
        Kt[b][d][j] = KV[(size_t)(j * 2 + b) * 512 + hc + d];
    }
    for (int idx = tid; idx < 2 * 100 * 32; idx += 256) {
        int d = idx & 31; int t = idx >> 5; int j = t % 100; int b = t / 100;
        Vs[b][j][d] = KV[(size_t)(j * 2 + b) * 512 + 256 + hc + d];
    }
    __syncthreads();

    const int w = tid >> 5, lane = tid & 31;
    const float scale = 0.17677669529663687f;

    for (int p = w; p < 200; p += 8) {
        int li = p >> 1, b = p & 1;
        int i = i0 + li;
        float q = Q[(size_t)(i * 2 + b) * 256 + hc + lane];
        float s0 = 0.f, s1 = 0.f, s2 = 0.f, s3 = 0.f;
#pragma unroll
        for (int d = 0; d < 32; d++) {
            float qd = __shfl_sync(0xffffffffu, q, d);
            s0 += qd * Kt[b][d][lane];
            s1 += qd * Kt[b][d][lane + 32];
            s2 += qd * Kt[b][d][lane + 64];
            if (lane < 4) s3 += qd * Kt[b][d][lane + 96];
        }
        s0 *= scale; s1 *= scale; s2 *= scale;
        s3 = (lane < 4) ? s3 * scale : -1e30f;
        float m = fmaxf(fmaxf(s0, s1), fmaxf(s2, s3));
#pragma unroll
        for (int o = 16; o; o >>= 1) m = fmaxf(m, __shfl_xor_sync(0xffffffffu, m, o));
        float e0 = __expf(s0 - m), e1 = __expf(s1 - m), e2 = __expf(s2 - m);
        float e3 = (lane < 4) ? __expf(s3 - m) : 0.f;
        float sum = e0 + e1 + e2 + e3;
#pragma unroll
        for (int o = 16; o; o >>= 1) sum += __shfl_xor_sync(0xffffffffu, sum, o);
        float inv = 1.0f / sum;
        float a0 = e0 * inv, a1 = e1 * inv, a2 = e2 * inv, a3 = e3 * inv;

        float oa = 0.f;
#pragma unroll
        for (int jj = 0; jj < 32; jj++) {
            float a = __shfl_sync(0xffffffffu, a0, jj);
            oa += a * Vs[b][jj][lane];
        }
#pragma unroll
        for (int jj = 0; jj < 32; jj++) {
            float a = __shfl_sync(0xffffffffu, a1, jj);
            oa += a * Vs[b][32 + jj][lane];
        }
#pragma unroll
        for (int jj = 0; jj < 32; jj++) {
            float a = __shfl_sync(0xffffffffu, a2, jj);
            oa += a * Vs[b][64 + jj][lane];
        }
#pragma unroll
        for (int jj = 0; jj < 4; jj++) {
            float a = __shfl_sync(0xffffffffu, a3, jj);
            oa += a * Vs[b][96 + jj][lane];
        }
        out[(size_t)(i * 2 + b) * 256 + hc + lane] = oa;
    }
}

// ---------------- launch ----------------
extern "C" void kernel_launch(void* const* d_in, const int* in_sizes, int n_in,
                              void* d_out, int out_size) {
    const float* x       = (const float*)d_in[0];
    const float* gat_W   = (const float*)d_in[1];   // [2][4][256][256]
    const float* gat_b   = (const float*)d_in[2];   // [2][4][256]
    // d_in[3] = gat_rel: edge bias constant along batch softmax axis -> cancels exactly
    const float* cross_W = (const float*)d_in[4];
    const float* cross_b = (const float*)d_in[5];
    const float* ln_g    = (const float*)d_in[6];
    const float* ln_b    = (const float*)d_in[7];
    float* out = (float*)d_out;

    float *Gn, *Ln, *qkvg, *qkvl, *att, *attg, *proj, *projg, *gout, *lout, *qc, *kvc, *catt, *cprj;
    cudaGetSymbolAddress((void**)&Gn,    d_Gn);
    cudaGetSymbolAddress((void**)&Ln,    d_Ln);
    cudaGetSymbolAddress((void**)&qkvg,  d_qkvg);
    cudaGetSymbolAddress((void**)&qkvl,  d_qkvl);
    cudaGetSymbolAddress((void**)&att,   d_att);
    cudaGetSymbolAddress((void**)&attg,  d_attg);
    cudaGetSymbolAddress((void**)&proj,  d_proj);
    cudaGetSymbolAddress((void**)&projg, d_projg);
    cudaGetSymbolAddress((void**)&gout,  d_gout);
    cudaGetSymbolAddress((void**)&lout,  d_lout);
    cudaGetSymbolAddress((void**)&qc,    d_qc);
    cudaGetSymbolAddress((void**)&kvc,   d_kvc);
    cudaGetSymbolAddress((void**)&catt,  d_catt);
    cudaGetSymbolAddress((void**)&cprj,  d_cprj);

    const int W2 = 256 * 256;
    const int ATTN_SMEM = (3 * 64 * 68 + 64 * 76) * 4;   // 71680 bytes
    cudaFuncSetAttribute(gat_attn_mma, cudaFuncAttributeMaxDynamicSharedMemorySize, ATTN_SMEM);

    // node construction (pool + transpose merged)
    prep_kernel<<<1800, 256>>>(x, Gn, Ln);

    // qkv projections (local + global merged), 3xTF32 tensor GEMM
    gemm_dual_kernel<<<dim3(12, 54), 256>>>(
        Ln, gat_W + 4 * W2, gat_b + 1024, qkvl, ML, 768,
        Gn, gat_W,          gat_b,        qkvg, MG, 768, 50);

    // GAT attention (tf32 MMA, local x<25 + global x>=25)
    gat_attn_mma<<<dim3(27, HEADS), 256, ATTN_SMEM>>>(qkvl, att, qkvg, attg);

    // out projections (merged)
    gemm_dual_kernel<<<dim3(4, 54), 256>>>(
        att,  gat_W + 7 * W2, gat_b + 1024 + 768, proj,  ML, 256,
        attg, gat_W + 3 * W2, gat_b + 768,        projg, MG, 256, 50);

    // add + LN (merged)
    add_ln_dual<<<ML + MG, 256>>>(proj, Ln, projg, Gn, ln_g, ln_b, lout, gout);

    // cross projections: Q (local) + KV (global, 100 distinct keys) merged
    gemm_dual_kernel<<<dim3(8, 54), 256>>>(
        lout, cross_W,      cross_b,       qc,  ML, 256,
        gout, cross_W + W2, cross_b + 256, kvc, MG, 512, 50);

    cross_attn_kernel<<<dim3(16, HEADS), 256>>>(qc, kvc, catt);
    gemm_bias_kernel<<<dim3(4, 50), 256>>>(catt, cross_W + 3 * W2, cross_b + 768, cprj, ML, 256);
    add_ln_tr_kernel<<<200, 512>>>(cprj, lout, ln_g + 512, ln_b + 512, out);
}